// round 2
// baseline (speedup 1.0000x reference)
#include <cuda_runtime.h>
#include <cuda_bf16.h>
#include <cstdint>

#define C_DIM   128
#define N_COMP  16
#define BM      128
#define THREADS 256
#define LDB     136                    // padded bf16 row stride (272B, 16B-mult)
#define XSZ     (128 * LDB)            // one bf16 tile, in elements

__device__ __forceinline__ uint32_t smem_u32(const void* p) {
    uint32_t a;
    asm("{ .reg .u64 t; cvta.to.shared.u64 t, %1; cvt.u32.u64 %0, t; }"
        : "=r"(a) : "l"(p));
    return a;
}

__device__ __forceinline__ void ldmx4(uint32_t& r0, uint32_t& r1,
                                      uint32_t& r2, uint32_t& r3, uint32_t addr) {
    asm volatile("ldmatrix.sync.aligned.m8n8.x4.shared.b16 {%0,%1,%2,%3}, [%4];"
                 : "=r"(r0), "=r"(r1), "=r"(r2), "=r"(r3) : "r"(addr));
}

__device__ __forceinline__ void mma16816(float* c, const uint32_t* a,
                                         uint32_t b0, uint32_t b1) {
    asm volatile(
        "mma.sync.aligned.m16n8k16.row.col.f32.bf16.bf16.f32 "
        "{%0,%1,%2,%3}, {%4,%5,%6,%7}, {%8,%9}, {%0,%1,%2,%3};"
        : "+f"(c[0]), "+f"(c[1]), "+f"(c[2]), "+f"(c[3])
        : "r"(a[0]), "r"(a[1]), "r"(a[2]), "r"(a[3]), "r"(b0), "r"(b1));
}

// One CTA: one l-value, 128 rows of that l's row space, full 128-col output.
// SMEM: Xh, Xl [128 x 128 bf16, stride 136]; WhT, WlT as [n][k] (B col-major).
// out = Xh@Wh + Xl@Wh + Xh@Wl  (bf16 split-precision, fp32 accumulate)
__global__ __launch_bounds__(THREADS, 1)
void tp_linear_mma(const float* __restrict__ x,
                   const float* __restrict__ w,
                   const float* __restrict__ pw,
                   float* __restrict__ out,
                   int n_nodes, int b1, int b2, int b3)
{
    extern __shared__ __nv_bfloat16 smem[];
    __nv_bfloat16* Xh = smem;
    __nv_bfloat16* Xl = smem + XSZ;
    __nv_bfloat16* Wh = smem + 2 * XSZ;   // transposed: [n][k]
    __nv_bfloat16* Wl = smem + 3 * XSZ;

    int tile = blockIdx.x;
    int l, tl;
    if (tile < b1)      { l = 0; tl = tile; }
    else if (tile < b2) { l = 1; tl = tile - b1; }
    else if (tile < b3) { l = 2; tl = tile - b2; }
    else                { l = 3; tl = tile - b3; }
    const int cl     = 2 * l + 1;
    const int mbase  = l * l;
    const int rows_l = n_nodes * cl;
    const int row0   = tl * BM;

    const int tid   = threadIdx.x;
    const float scale = __ldg(&pw[l]);

    // ---- stage X tile -> bf16 hi/lo (zero-padded OOB rows) ----
    {
        const float4* x4 = (const float4*)x;
        for (int idx = tid; idx < BM * (C_DIM / 4); idx += THREADS) {
            int lr = idx >> 5;
            int v  = idx & 31;
            int r  = row0 + lr;
            float4 val = make_float4(0.f, 0.f, 0.f, 0.f);
            if (r < rows_l) {
                int node = r / cl;
                int m    = mbase + (r - node * cl);
                val = x4[((size_t)node * N_COMP + m) * (C_DIM / 4) + v];
            }
            float fv[4] = {val.x, val.y, val.z, val.w};
            __nv_bfloat16 h[4], lo[4];
            #pragma unroll
            for (int j = 0; j < 4; j++) {
                h[j]  = __float2bfloat16(fv[j]);
                lo[j] = __float2bfloat16(fv[j] - __bfloat162float(h[j]));
            }
            int off = lr * LDB + v * 4;
            *(__nv_bfloat162*)(Xh + off)     = __nv_bfloat162(h[0],  h[1]);
            *(__nv_bfloat162*)(Xh + off + 2) = __nv_bfloat162(h[2],  h[3]);
            *(__nv_bfloat162*)(Xl + off)     = __nv_bfloat162(lo[0], lo[1]);
            *(__nv_bfloat162*)(Xl + off + 2) = __nv_bfloat162(lo[2], lo[3]);
        }
    }

    // ---- stage W[l]*pw -> bf16 hi/lo, transposed to [n][k] ----
    {
        const float4* w4 = (const float4*)(w + (size_t)l * C_DIM * C_DIM);
        for (int idx = tid; idx < C_DIM * (C_DIM / 4); idx += THREADS) {
            int k = idx >> 5;
            int v = idx & 31;
            float4 ww = w4[idx];
            float fv[4] = {ww.x * scale, ww.y * scale, ww.z * scale, ww.w * scale};
            #pragma unroll
            for (int j = 0; j < 4; j++) {
                __nv_bfloat16 h  = __float2bfloat16(fv[j]);
                __nv_bfloat16 lo = __float2bfloat16(fv[j] - __bfloat162float(h));
                int n = v * 4 + j;
                Wh[n * LDB + k] = h;
                Wl[n * LDB + k] = lo;
            }
        }
    }
    __syncthreads();

    // ---- warp tiling: 8 warps = 4 row-blocks x 2 col-blocks ----
    const int lane = tid & 31;
    const int warp = tid >> 5;
    const int wr   = warp >> 1;       // 0..3 -> 32-row block
    const int wc   = warp & 1;        // 0..1 -> 64-col block

    // ldmatrix lane offsets (element units; *2 for bytes)
    // A (row-major m16 x k16 tile): lanes 0-15 -> rows, k+0; 16-31 -> rows, k+8
    const int a_r  = lane & 15;
    const int a_c8 = (lane >> 4) * 8;
    uint32_t a_off[2];
    #pragma unroll
    for (int mt = 0; mt < 2; mt++)
        a_off[mt] = (uint32_t)(((wr * 32 + mt * 16 + a_r) * LDB + a_c8) * 2);

    // B ([n][k] rows): pair p covers n-tiles 2p,2p+1
    const int bg  = lane >> 3;              // 0..3
    const int blr = lane & 7;
    const int b_n = ((bg >> 1) * 8) + blr;  // +0 or +8 within pair
    const int b_c8 = (bg & 1) * 8;
    uint32_t b_off[4];
    #pragma unroll
    for (int p = 0; p < 4; p++)
        b_off[p] = (uint32_t)(((wc * 64 + p * 16 + b_n) * LDB + b_c8) * 2);

    const uint32_t xh_base = smem_u32(Xh);
    const uint32_t xl_base = smem_u32(Xl);
    const uint32_t wh_base = smem_u32(Wh);
    const uint32_t wl_base = smem_u32(Wl);

    float acc[2][8][4];
    #pragma unroll
    for (int mt = 0; mt < 2; mt++)
        #pragma unroll
        for (int nt = 0; nt < 8; nt++)
            #pragma unroll
            for (int j = 0; j < 4; j++) acc[mt][nt][j] = 0.f;

    const uint32_t aBases[3] = {xh_base, xl_base, xh_base};
    const uint32_t bBases[3] = {wh_base, wh_base, wl_base};

    #pragma unroll
    for (int pass = 0; pass < 3; pass++) {
        const uint32_t ab = aBases[pass];
        const uint32_t bb = bBases[pass];
        #pragma unroll
        for (int ks = 0; ks < 8; ks++) {
            const uint32_t kadd = ks * 32;   // 16 bf16 = 32 bytes
            uint32_t a[2][4];
            #pragma unroll
            for (int mt = 0; mt < 2; mt++)
                ldmx4(a[mt][0], a[mt][1], a[mt][2], a[mt][3],
                      ab + a_off[mt] + kadd);
            uint32_t bfr[8][2];
            #pragma unroll
            for (int p = 0; p < 4; p++) {
                uint32_t r0, r1, r2, r3;
                ldmx4(r0, r1, r2, r3, bb + b_off[p] + kadd);
                bfr[2*p][0]   = r0; bfr[2*p][1]   = r1;
                bfr[2*p+1][0] = r2; bfr[2*p+1][1] = r3;
            }
            #pragma unroll
            for (int mt = 0; mt < 2; mt++)
                #pragma unroll
                for (int nt = 0; nt < 8; nt++)
                    mma16816(acc[mt][nt], a[mt], bfr[nt][0], bfr[nt][1]);
        }
    }

    // ---- epilogue: C frag -> gmem (float2 stores, row-bounds masked) ----
    const int grp = lane >> 2;
    const int qid = lane & 3;
    #pragma unroll
    for (int mt = 0; mt < 2; mt++) {
        #pragma unroll
        for (int h = 0; h < 2; h++) {
            int r = row0 + wr * 32 + mt * 16 + grp + h * 8;
            if (r < rows_l) {
                int node = r / cl;
                int m    = mbase + (r - node * cl);
                float* orow = out + ((size_t)node * N_COMP + m) * C_DIM
                                  + wc * 64 + qid * 2;
                #pragma unroll
                for (int nt = 0; nt < 8; nt++) {
                    float2 v = make_float2(acc[mt][nt][h*2], acc[mt][nt][h*2+1]);
                    *(float2*)(orow + nt * 8) = v;
                }
            }
        }
    }
}

extern "C" void kernel_launch(void* const* d_in, const int* in_sizes, int n_in,
                              void* d_out, int out_size) {
    const float* x  = (const float*)d_in[0];
    const float* w  = (const float*)d_in[1];
    const float* pw = (const float*)d_in[2];
    float* out = (float*)d_out;

    const int n_nodes = in_sizes[0] / (N_COMP * C_DIM);

    int t0 = (n_nodes * 1 + BM - 1) / BM;
    int t1 = (n_nodes * 3 + BM - 1) / BM;
    int t2 = (n_nodes * 5 + BM - 1) / BM;
    int t3 = (n_nodes * 7 + BM - 1) / BM;
    int b1 = t0, b2 = t0 + t1, b3 = t0 + t1 + t2;
    int grid = b3 + t3;

    size_t smem_bytes = (size_t)4 * XSZ * sizeof(__nv_bfloat16); // 139264 B
    cudaFuncSetAttribute(tp_linear_mma,
                         cudaFuncAttributeMaxDynamicSharedMemorySize,
                         (int)smem_bytes);

    tp_linear_mma<<<grid, THREADS, smem_bytes>>>(x, w, pw, out,
                                                 n_nodes, b1, b2, b3);
}

// round 4
// speedup vs baseline: 3.4127x; 3.4127x over previous
#include <cuda_runtime.h>
#include <cuda_bf16.h>
#include <cstdint>

#define C_DIM   128
#define N_COMP  16
#define BM      128
#define THREADS 512

// smem byte map (dynamic, 192KB):
//   Xh   @      0  (32KB: two k-halves of [128r][64k] bf16, swizzled 128B rows)
//   Xl   @  32768
//   Wh   @  65536  ([128n][128k] bf16 as two k-halves, same layout)
//   Wl   @  98304
//   raw  @ 131072  (64KB: next x tile, f32 [128][128])
#define OFF_XH  0
#define OFF_XL  32768
#define OFF_WH  65536
#define OFF_WL  98304
#define OFF_RAW 131072
#define HALF_BYTES 16384   // one k-half of a 128-row tile (128 rows * 128B)

__device__ __forceinline__ uint32_t smem_u32(const void* p) {
    uint32_t a;
    asm("{ .reg .u64 t; cvta.to.shared.u64 t, %1; cvt.u32.u64 %0, t; }"
        : "=r"(a) : "l"(p));
    return a;
}

__device__ __forceinline__ void ldmx4(uint32_t& r0, uint32_t& r1,
                                      uint32_t& r2, uint32_t& r3, uint32_t addr) {
    asm volatile("ldmatrix.sync.aligned.m8n8.x4.shared.b16 {%0,%1,%2,%3}, [%4];"
                 : "=r"(r0), "=r"(r1), "=r"(r2), "=r"(r3) : "r"(addr));
}

__device__ __forceinline__ void mma16816(float* c, const uint32_t* a,
                                         uint32_t b0, uint32_t b1) {
    asm volatile(
        "mma.sync.aligned.m16n8k16.row.col.f32.bf16.bf16.f32 "
        "{%0,%1,%2,%3}, {%4,%5,%6,%7}, {%8,%9}, {%0,%1,%2,%3};"
        : "+f"(c[0]), "+f"(c[1]), "+f"(c[2]), "+f"(c[3])
        : "r"(a[0]), "r"(a[1]), "r"(a[2]), "r"(a[3]), "r"(b0), "r"(b1));
}

// swizzled byte offset within a tile: row-major 128B rows per k-half,
// 16B chunks XOR-permuted by (row & 7).  k in [0,128), row in [0,128).
__device__ __forceinline__ uint32_t swz_off(int row, int k) {
    return ((uint32_t)(k >> 6) << 14) + ((uint32_t)row << 7)
         + ((uint32_t)((((k & 63) >> 3) ^ (row & 7))) << 4)
         + (uint32_t)((k & 7) << 1);
}

// Persistent kernel: each CTA owns one l, loads W[l]*pw hi/lo once, then loops
// over 128-row x-tiles of that l.  out = Xh@Wh + Xl@Wh + Xh@Wl, fp32 acc.
__global__ __launch_bounds__(THREADS, 1)
void tp_persist(const float* __restrict__ x,
                const float* __restrict__ w,
                const float* __restrict__ pw,
                float* __restrict__ out,
                int n_nodes, int4 gcum, int4 gsz4)
{
    extern __shared__ __align__(128) char smem[];
    const uint32_t sb = smem_u32(smem);

    const int tid  = threadIdx.x;
    const int lane = tid & 31;
    const int warp = tid >> 5;

    // ---- l assignment (static proportional partition of the grid) ----
    int bid = blockIdx.x, l, rank, gsz;
    if (bid < gcum.y)      { l = 0; rank = bid - gcum.x; gsz = gsz4.x; }
    else if (bid < gcum.z) { l = 1; rank = bid - gcum.y; gsz = gsz4.y; }
    else if (bid < gcum.w) { l = 2; rank = bid - gcum.z; gsz = gsz4.z; }
    else                   { l = 3; rank = bid - gcum.w; gsz = gsz4.w; }
    const int cl     = 2 * l + 1;
    const int mbase  = l * l;
    const int rows_l = n_nodes * cl;
    const int t_l    = (rows_l + BM - 1) / BM;

    // ---- stage W[l]*pw -> bf16 hi/lo, B layout [n][k], swizzled (once) ----
    {
        const float scale = __ldg(&pw[l]);
        const float* wp = w + (size_t)l * C_DIM * C_DIM;
        #pragma unroll
        for (int e = tid; e < C_DIM * C_DIM; e += THREADS) {
            int k = e >> 7, n = e & 127;           // w[k][n], coalesced read
            float v = wp[e] * scale;
            __nv_bfloat16 h  = __float2bfloat16(v);
            __nv_bfloat16 lo = __float2bfloat16(v - __bfloat162float(h));
            uint32_t off = swz_off(n, k);
            *(__nv_bfloat16*)(smem + OFF_WH + off) = h;
            *(__nv_bfloat16*)(smem + OFF_WL + off) = lo;
        }
    }

    if (rank >= t_l) return;   // uniform per-CTA, safe

    // ---- prefetch helper: raw f32 tile via cp.async (zfill OOB rows) ----
    const float4* x4 = (const float4*)x;
    auto prefetch = [&](int tl) {
        int row0 = tl * BM;
        #pragma unroll
        for (int j = 0; j < 8; j++) {
            int idx = tid + j * THREADS;          // 0..4095
            int r = row0 + (idx >> 5);
            int v = idx & 31;
            const float4* src = x4;
            int sz = 0;
            if (r < rows_l) {
                int node = r / cl;
                int m    = mbase + (r - node * cl);
                src = x4 + ((size_t)node * N_COMP + m) * 32 + v;
                sz = 16;
            }
            uint32_t dst = sb + OFF_RAW + idx * 16;
            asm volatile("cp.async.cg.shared.global [%0], [%1], 16, %2;"
                         :: "r"(dst), "l"(src), "r"(sz));
        }
        asm volatile("cp.async.commit_group;");
    };

    prefetch(rank);

    // ---- per-thread fragment addressing (swizzle-aware) ----
    const int wr = warp & 3;          // 32-row block
    const int wc = warp >> 2;         // 32-col block
    // A: lanes 0-15 rows, lane>>4 selects k-chunk (+8)
    const int a_hi = lane >> 4;
    int a_row[2], a_s[2];
    #pragma unroll
    for (int mt = 0; mt < 2; mt++) {
        a_row[mt] = wr * 32 + mt * 16 + (lane & 15);
        a_s[mt]   = a_row[mt] & 7;
    }
    // B (round-2 verified mapping): bg=lane>>3; rows (bg>>1)*8+(lane&7); k-chunk bg&1
    const int bg   = lane >> 3;
    const int b_hi = bg & 1;
    int b_row[2], b_s[2];
    #pragma unroll
    for (int nt = 0; nt < 2; nt++) {
        b_row[nt] = wc * 32 + nt * 16 + ((bg >> 1) * 8) + (lane & 7);
        b_s[nt]   = b_row[nt] & 7;
    }

    const int grp = lane >> 2;        // epilogue C-frag row
    const int qid = lane & 3;         // epilogue C-frag col pair

    // ---- persistent tile loop ----
    for (int tl = rank; tl < t_l; tl += gsz) {
        const int row0 = tl * BM;

        asm volatile("cp.async.wait_group 0;" ::: "memory");
        __syncthreads();

        // convert raw f32 -> Xh/Xl bf16 swizzled
        {
            const float4* raw4 = (const float4*)(smem + OFF_RAW);
            #pragma unroll
            for (int j = 0; j < 8; j++) {
                int idx = tid + j * THREADS;
                int r = idx >> 5, v = idx & 31;
                float4 f = raw4[idx];
                __nv_bfloat162 h0 = __floats2bfloat162_rn(f.x, f.y);
                __nv_bfloat162 h1 = __floats2bfloat162_rn(f.z, f.w);
                __nv_bfloat162 l0 = __floats2bfloat162_rn(
                    f.x - __bfloat162float(__low2bfloat16(h0)),
                    f.y - __bfloat162float(__high2bfloat16(h0)));
                __nv_bfloat162 l1 = __floats2bfloat162_rn(
                    f.z - __bfloat162float(__low2bfloat16(h1)),
                    f.w - __bfloat162float(__high2bfloat16(h1)));
                uint32_t off = swz_off(r, v * 4);   // 8B within one 16B chunk
                uint2 uh, ul;
                uh.x = *(uint32_t*)&h0; uh.y = *(uint32_t*)&h1;
                ul.x = *(uint32_t*)&l0; ul.y = *(uint32_t*)&l1;
                *(uint2*)(smem + OFF_XH + off) = uh;
                *(uint2*)(smem + OFF_XL + off) = ul;
            }
        }
        __syncthreads();

        // prefetch next tile while we compute this one
        int nxt = tl + gsz;
        if (nxt < t_l) prefetch(nxt);

        // ---- fused 3-product mainloop over 8 k16-steps ----
        float acc[2][4][4];
        #pragma unroll
        for (int mt = 0; mt < 2; mt++)
            #pragma unroll
            for (int n8 = 0; n8 < 4; n8++)
                #pragma unroll
                for (int j = 0; j < 4; j++) acc[mt][n8][j] = 0.f;

        #pragma unroll 2
        for (int ks = 0; ks < 8; ks++) {
            const uint32_t hoff = (ks & 4) ? HALF_BYTES : 0u;
            const int c0 = (ks & 3) * 2;

            uint32_t Ah[2][4], Al[2][4];
            #pragma unroll
            for (int mt = 0; mt < 2; mt++) {
                uint32_t a = sb + hoff + (uint32_t)(a_row[mt] << 7)
                           + (uint32_t)((((c0 | a_hi) ^ a_s[mt])) << 4);
                ldmx4(Ah[mt][0], Ah[mt][1], Ah[mt][2], Ah[mt][3], a + OFF_XH);
                ldmx4(Al[mt][0], Al[mt][1], Al[mt][2], Al[mt][3], a + OFF_XL);
            }
            uint32_t Bh[2][4], Bl[2][4];
            #pragma unroll
            for (int nt = 0; nt < 2; nt++) {
                uint32_t b = sb + hoff + (uint32_t)(b_row[nt] << 7)
                           + (uint32_t)((((c0 | b_hi) ^ b_s[nt])) << 4);
                ldmx4(Bh[nt][0], Bh[nt][1], Bh[nt][2], Bh[nt][3], b + OFF_WH);
                ldmx4(Bl[nt][0], Bl[nt][1], Bl[nt][2], Bl[nt][3], b + OFF_WL);
            }
            #pragma unroll
            for (int mt = 0; mt < 2; mt++)
                #pragma unroll
                for (int n8 = 0; n8 < 4; n8++) {
                    const int nt = n8 >> 1, p = (n8 & 1) * 2;
                    mma16816(acc[mt][n8], Ah[mt], Bh[nt][p], Bh[nt][p + 1]);
                    mma16816(acc[mt][n8], Al[mt], Bh[nt][p], Bh[nt][p + 1]);
                    mma16816(acc[mt][n8], Ah[mt], Bl[nt][p], Bl[nt][p + 1]);
                }
        }

        // ---- epilogue: C frags -> gmem (float2, row-masked) ----
        #pragma unroll
        for (int mt = 0; mt < 2; mt++) {
            #pragma unroll
            for (int h = 0; h < 2; h++) {
                int r = row0 + wr * 32 + mt * 16 + grp + h * 8;
                if (r < rows_l) {
                    int node = r / cl;
                    int m    = mbase + (r - node * cl);
                    float* orow = out + ((size_t)node * N_COMP + m) * C_DIM
                                      + wc * 32 + qid * 2;
                    #pragma unroll
                    for (int n8 = 0; n8 < 4; n8++) {
                        float2 v2 = make_float2(acc[mt][n8][h * 2],
                                                acc[mt][n8][h * 2 + 1]);
                        *(float2*)(orow + n8 * 8) = v2;
                    }
                }
            }
        }
    }
}

extern "C" void kernel_launch(void* const* d_in, const int* in_sizes, int n_in,
                              void* d_out, int out_size) {
    const float* x  = (const float*)d_in[0];
    const float* w  = (const float*)d_in[1];
    const float* pw = (const float*)d_in[2];
    float* out = (float*)d_out;

    const int n_nodes = in_sizes[0] / (N_COMP * C_DIM);

    int dev = 0, nsm = 148;
    cudaGetDevice(&dev);
    cudaDeviceGetAttribute(&nsm, cudaDevAttrMultiProcessorCount, dev);

    long long t[4], T = 0;
    for (int l = 0; l < 4; l++) {
        t[l] = ((long long)n_nodes * (2 * l + 1) + BM - 1) / BM;
        T += t[l];
    }
    int g[4], used = 0;
    for (int l = 0; l < 3; l++) {
        g[l] = (int)(((long long)nsm * t[l]) / T);
        if (g[l] < 1) g[l] = 1;
        used += g[l];
    }
    g[3] = nsm - used;
    if (g[3] < 1) g[3] = 1;

    int4 gcum = make_int4(0, g[0], g[0] + g[1], g[0] + g[1] + g[2]);
    int4 gsz4 = make_int4(g[0], g[1], g[2], g[3]);
    int grid = g[0] + g[1] + g[2] + g[3];

    size_t smem_bytes = 196608;   // 192KB
    cudaFuncSetAttribute(tp_persist,
                         cudaFuncAttributeMaxDynamicSharedMemorySize,
                         (int)smem_bytes);

    tp_persist<<<grid, THREADS, smem_bytes>>>(x, w, pw, out,
                                              n_nodes, gcum, gsz4);
}